// round 1
// baseline (speedup 1.0000x reference)
#include <cuda_runtime.h>

// Problem constants (fixed by the dataset)
#define NN 30000
#define TT 4
#define FF 128
#define HH 8
#define DD 16

// Scratch (no cudaMalloc allowed): intermediates + type buckets.
__device__ float g_node_p[NN * FF];        // [N,F]   node projections
__device__ float g_edge_p[NN * TT * FF];   // [N,T,F] edge projections
__device__ int   g_lists[TT][NN];          // per-type node index lists
__device__ int   g_counts[TT];

// ---------------------------------------------------------------------------
// Bucket nodes by type. Output is deterministic even though list order is not:
// each node's downstream math is independent of its slot.
// ---------------------------------------------------------------------------
__global__ void k_zero() {
    if (threadIdx.x < TT) g_counts[threadIdx.x] = 0;
}

__global__ void k_scatter(const int* __restrict__ mask, int n) {
    int i = blockIdx.x * blockDim.x + threadIdx.x;
    if (i < n) {
        int t = mask[i];
        int p = atomicAdd(&g_counts[t], 1);
        g_lists[t][p] = i;
    }
}

// ---------------------------------------------------------------------------
// Grouped projection GEMM.
// Block = (chunk of 128 nodes of type t) x (matrix j: j<4 edge, j==4 node).
// C[i,g] = sum_f A[i,f] * M[g,f]   (both K-major in gmem)
// 256 threads, 8x8 register tile, KT=32 SMEM K-tiles (SMEM ~34 KB).
// ---------------------------------------------------------------------------
#define KT 32

__global__ __launch_bounds__(256, 2) void k_gemm(
    const float* __restrict__ feature,    // [N,F]
    const float* __restrict__ edge_fea,   // [N,T,F]
    const float* __restrict__ node_proj,  // [T,F,F]
    const float* __restrict__ edge_proj)  // [T*T,F,F]
{
    const int t = blockIdx.y;
    const int j = blockIdx.z;           // 0..3 edge slot, 4 = node
    const int cnt = g_counts[t];
    const int start = blockIdx.x * 128;
    if (start >= cnt) return;

    __shared__ float As[KT][132];       // A^T tile: [f_local][node]
    __shared__ float Ms[KT][132];       // M^T tile: [f_local][g]
    __shared__ int   rows[128];

    const int tid = threadIdx.x;
    if (tid < 128) {
        int idx = start + tid;
        rows[tid] = (idx < cnt) ? g_lists[t][idx] : -1;
    }
    __syncthreads();

    const float* M = (j == 4) ? (node_proj + (size_t)t * FF * FF)
                              : (edge_proj + ((size_t)t * TT + j) * FF * FF);

    float acc[8][8];
#pragma unroll
    for (int a = 0; a < 8; a++)
#pragma unroll
        for (int b = 0; b < 8; b++) acc[a][b] = 0.f;

    const int tx = tid & 15;            // 16 col-groups of 8
    const int ty = tid >> 4;            // 16 row-groups of 8

    for (int k0 = 0; k0 < FF; k0 += KT) {
        // --- load A tile (gathered node vectors), transposed into SMEM ---
#pragma unroll
        for (int s = 0; s < 4; s++) {
            int slot = tid + s * 256;   // 0..1023 float4 slots
            int i  = slot >> 3;         // node row 0..127
            int fq = slot & 7;          // float4 within 32-float K-slice
            int r  = rows[i];
            float4 v = make_float4(0.f, 0.f, 0.f, 0.f);
            if (r >= 0) {
                const float* src = (j == 4)
                    ? (feature + (size_t)r * FF)
                    : (edge_fea + ((size_t)r * TT + j) * FF);
                v = *(const float4*)(src + k0 + fq * 4);
            }
            As[fq * 4 + 0][i] = v.x;
            As[fq * 4 + 1][i] = v.y;
            As[fq * 4 + 2][i] = v.z;
            As[fq * 4 + 3][i] = v.w;
        }
        // --- load M tile, transposed into SMEM ---
#pragma unroll
        for (int s = 0; s < 4; s++) {
            int slot = tid + s * 256;
            int g  = slot >> 3;
            int fq = slot & 7;
            float4 v = *(const float4*)(M + (size_t)g * FF + k0 + fq * 4);
            Ms[fq * 4 + 0][g] = v.x;
            Ms[fq * 4 + 1][g] = v.y;
            Ms[fq * 4 + 2][g] = v.z;
            Ms[fq * 4 + 3][g] = v.w;
        }
        __syncthreads();

#pragma unroll
        for (int f = 0; f < KT; f++) {
            float a[8], b[8];
#pragma unroll
            for (int q = 0; q < 8; q += 4) {
                float4 va = *(const float4*)&As[f][ty * 8 + q];
                a[q] = va.x; a[q + 1] = va.y; a[q + 2] = va.z; a[q + 3] = va.w;
                float4 vb = *(const float4*)&Ms[f][tx * 8 + q];
                b[q] = vb.x; b[q + 1] = vb.y; b[q + 2] = vb.z; b[q + 3] = vb.w;
            }
#pragma unroll
            for (int ii = 0; ii < 8; ii++)
#pragma unroll
                for (int gg = 0; gg < 8; gg++)
                    acc[ii][gg] += a[ii] * b[gg];
        }
        __syncthreads();
    }

    // --- scatter results back per node ---
#pragma unroll
    for (int ii = 0; ii < 8; ii++) {
        int r = rows[ty * 8 + ii];
        if (r < 0) continue;
        float* dst = (j == 4) ? (g_node_p + (size_t)r * FF)
                              : (g_edge_p + ((size_t)r * TT + j) * FF);
#pragma unroll
        for (int gg = 0; gg < 8; gg += 4) {
            *(float4*)(dst + tx * 8 + gg) =
                make_float4(acc[ii][gg], acc[ii][gg + 1],
                            acc[ii][gg + 2], acc[ii][gg + 3]);
        }
    }
}

// ---------------------------------------------------------------------------
// Scores + softmax over the HEAD axis (reference: softmax(dim=1) on [N,H,1,T]).
// One warp per node. lane = t*8 + h. Score = <node_p[h], edge_p[t,h]> / sqrt(D).
// Softmax over h == reduction over each 8-lane subgroup (shfl width=8).
// Output layout [N,T,H]: out[n*32 + t*8 + h] — matches lane order exactly.
// ---------------------------------------------------------------------------
__global__ void k_attn(float* __restrict__ out, int n) {
    int warp = (int)((blockIdx.x * blockDim.x + threadIdx.x) >> 5);
    int lane = threadIdx.x & 31;
    if (warp >= n) return;
    int t = lane >> 3;
    int h = lane & 7;

    const float* np = g_node_p + (size_t)warp * FF + h * DD;
    const float* ep = g_edge_p + ((size_t)warp * TT + t) * FF + h * DD;

    float s = 0.f;
#pragma unroll
    for (int q = 0; q < 4; q++) {
        float4 a = *(const float4*)(np + q * 4);
        float4 b = *(const float4*)(ep + q * 4);
        s += a.x * b.x + a.y * b.y + a.z * b.z + a.w * b.w;
    }
    s *= 0.25f;  // 1/sqrt(D), D=16

    float m = s;
#pragma unroll
    for (int o = 4; o >= 1; o >>= 1)
        m = fmaxf(m, __shfl_xor_sync(0xffffffffu, m, o, 8));
    float e = expf(s - m);
    float sum = e;
#pragma unroll
    for (int o = 4; o >= 1; o >>= 1)
        sum += __shfl_xor_sync(0xffffffffu, sum, o, 8);

    out[(size_t)warp * (TT * HH) + lane] = e / sum;
}

// ---------------------------------------------------------------------------
extern "C" void kernel_launch(void* const* d_in, const int* in_sizes, int n_in,
                              void* d_out, int out_size) {
    const float* feature   = (const float*)d_in[0];  // [N,F]
    const float* edge_fea  = (const float*)d_in[1];  // [N,T,F]
    const int*   mask      = (const int*)d_in[2];    // [N]
    const float* node_proj = (const float*)d_in[3];  // [T,F,F]
    const float* edge_proj = (const float*)d_in[4];  // [T*T,F,F]
    float* out = (float*)d_out;

    const int n = in_sizes[2];  // N from mask element count

    k_zero<<<1, 32>>>();
    k_scatter<<<(n + 255) / 256, 256>>>(mask, n);

    dim3 grid((n + 127) / 128, TT, 5);
    k_gemm<<<grid, 256>>>(feature, edge_fea, node_proj, edge_proj);

    // 8 warps / block
    k_attn<<<(n + 7) / 8, 256>>>(out, n);
}

// round 4
// speedup vs baseline: 1.3846x; 1.3846x over previous
#include <cuda_runtime.h>
#include <cuda_bf16.h>
#include <cstdint>

#define NN 30000
#define TT 4
#define FF 128
#define HH 8
#define DD 16

// Scratch (no cudaMalloc allowed)
__device__ float g_node_p[NN * FF];        // [N,F]
__device__ float g_edge_p[NN * TT * FF];   // [N,T,F]
__device__ int   g_lists[TT][NN];
__device__ int   g_counts[TT];

// ---------------------------------------------------------------------------
__global__ void k_zero() { if (threadIdx.x < TT) g_counts[threadIdx.x] = 0; }

__global__ void k_scatter(const int* __restrict__ mask, int n) {
    int i = blockIdx.x * blockDim.x + threadIdx.x;
    if (i < n) {
        int t = mask[i];
        int p = atomicAdd(&g_counts[t], 1);
        g_lists[t][p] = i;
    }
}

// ---------------------------------------------------------------------------
// Tensor-core grouped GEMM via mma.sync (HMMA path, works on sm_103 base).
// Block = (chunk of 128 nodes of type t) x (matrix j; j<4 edge, j==4 node).
// C[i,g] = sum_f A[i,f] * M[g,f]
// 3-term bf16 split: C = Ah*Mh + Ah*Ml + Al*Mh  (fp32-class accuracy).
//
// SMEM: 4 tiles of 128 rows x 128 bf16, row padded to 136 bf16 (272B = 68
// words) -> fragment LDS is bank-conflict-free (bank = (4r+ci) mod 32).
// M row-major [g][f] IS col-major B(k=f, n=g) for mma row.col: the two
// consecutive-k bf16 in each B register are contiguous in memory.
// ---------------------------------------------------------------------------
#define RSTRIDE 136                       // bf16 elems per padded row
#define TILE_BYTES (128 * RSTRIDE * 2)    // 34816
#define SM_AHI 0
#define SM_ALO TILE_BYTES
#define SM_MHI (2 * TILE_BYTES)
#define SM_MLO (3 * TILE_BYTES)
#define SM_ROWS (4 * TILE_BYTES)
#define SMEM_BYTES (4 * TILE_BYTES + 512)

__device__ __forceinline__ uint32_t pk(__nv_bfloat16 a, __nv_bfloat16 b) {
    __nv_bfloat162 t(a, b);
    return *(uint32_t*)&t;
}

// split-convert 4 floats -> hi uint2 + lo uint2
__device__ __forceinline__ void split4(float4 v, uint2& hi, uint2& lo) {
    __nv_bfloat16 h0 = __float2bfloat16_rn(v.x); float l0 = v.x - __bfloat162float(h0);
    __nv_bfloat16 h1 = __float2bfloat16_rn(v.y); float l1 = v.y - __bfloat162float(h1);
    __nv_bfloat16 h2 = __float2bfloat16_rn(v.z); float l2 = v.z - __bfloat162float(h2);
    __nv_bfloat16 h3 = __float2bfloat16_rn(v.w); float l3 = v.w - __bfloat162float(h3);
    hi = make_uint2(pk(h0, h1), pk(h2, h3));
    lo = make_uint2(pk(__float2bfloat16_rn(l0), __float2bfloat16_rn(l1)),
                    pk(__float2bfloat16_rn(l2), __float2bfloat16_rn(l3)));
}

__device__ __forceinline__ void mma16816(float* c, const uint32_t* a, const uint32_t* b) {
    asm volatile(
        "mma.sync.aligned.m16n8k16.row.col.f32.bf16.bf16.f32 "
        "{%0,%1,%2,%3}, {%4,%5,%6,%7}, {%8,%9}, {%0,%1,%2,%3};"
        : "+f"(c[0]), "+f"(c[1]), "+f"(c[2]), "+f"(c[3])
        : "r"(a[0]), "r"(a[1]), "r"(a[2]), "r"(a[3]), "r"(b[0]), "r"(b[1]));
}

__global__ __launch_bounds__(256, 1) void k_gemm_mma(
    const float* __restrict__ feature,    // [N,F]
    const float* __restrict__ edge_fea,   // [N,T,F]
    const float* __restrict__ node_proj,  // [T,F,F]
    const float* __restrict__ edge_proj)  // [T*T,F,F]
{
    extern __shared__ char smem[];
    const int t = blockIdx.y;
    const int j = blockIdx.z;
    const int cnt = g_counts[t];
    const int start = blockIdx.x * 128;
    if (start >= cnt) return;

    const int tid  = threadIdx.x;
    const int wid  = tid >> 5;
    const int lane = tid & 31;

    int* rows = (int*)(smem + SM_ROWS);
    if (tid < 128) {
        int idx = start + tid;
        rows[tid] = (idx < cnt) ? g_lists[t][idx] : -1;
    }
    __syncthreads();

    // ---- stage + split-convert: threads 0-127 do A row tid, 128-255 do M row ----
    {
        const int half = tid >> 7;
        const int row  = tid & 127;
        const float* src;
        char *dhi, *dlo;
        if (half == 0) {
            int r = rows[row];
            src = (r < 0) ? nullptr
                : ((j == 4) ? (feature + (size_t)r * FF)
                            : (edge_fea + ((size_t)r * TT + j) * FF));
            dhi = smem + SM_AHI; dlo = smem + SM_ALO;
        } else {
            const float* M = (j == 4) ? (node_proj + (size_t)t * FF * FF)
                                      : (edge_proj + ((size_t)t * TT + j) * FF * FF);
            src = M + (size_t)row * FF;
            dhi = smem + SM_MHI; dlo = smem + SM_MLO;
        }
        const uint32_t rb = (uint32_t)row * (RSTRIDE * 2);
#pragma unroll
        for (int c4 = 0; c4 < 32; c4++) {
            float4 v = src ? *(const float4*)(src + c4 * 4)
                           : make_float4(0.f, 0.f, 0.f, 0.f);
            uint2 hi, lo;
            split4(v, hi, lo);
            *(uint2*)(dhi + rb + c4 * 8) = hi;
            *(uint2*)(dlo + rb + c4 * 8) = lo;
        }
    }
    __syncthreads();

    // ---- warp tiles: 8 warps in 4(m) x 2(n); warp tile 32(m) x 64(n) ----
    const int m0 = (wid >> 1) * 32;
    const int n0 = (wid & 1) * 64;
    const int fr = lane >> 2;          // fragment row 0..7
    const int fc = lane & 3;           // fragment col-pair 0..3

    float acc[2][8][4];
#pragma unroll
    for (int mt = 0; mt < 2; mt++)
#pragma unroll
        for (int nt = 0; nt < 8; nt++)
#pragma unroll
            for (int q = 0; q < 4; q++) acc[mt][nt][q] = 0.f;

    // word pointers into the 4 tiles
    const uint32_t* Ah = (const uint32_t*)(smem + SM_AHI);
    const uint32_t* Al = (const uint32_t*)(smem + SM_ALO);
    const uint32_t* Mh = (const uint32_t*)(smem + SM_MHI);
    const uint32_t* Ml = (const uint32_t*)(smem + SM_MLO);
    const int RW = RSTRIDE / 2;        // 68 words per row

#pragma unroll
    for (int term = 0; term < 3; term++) {
        const uint32_t* At = (term == 2) ? Al : Ah;
        const uint32_t* Bt = (term == 1) ? Ml : Mh;
#pragma unroll
        for (int k0 = 0; k0 < 8; k0++) {
            const int kw = k0 * 8;     // k-step base in words (16 bf16)
            uint32_t a[2][4];
#pragma unroll
            for (int mt = 0; mt < 2; mt++) {
                const uint32_t* base = At + (m0 + mt * 16 + fr) * RW + kw + fc;
                a[mt][0] = base[0];
                a[mt][1] = base[8 * RW];
                a[mt][2] = base[4];
                a[mt][3] = base[8 * RW + 4];
            }
#pragma unroll
            for (int nt = 0; nt < 8; nt++) {
                uint32_t b[2];
                const uint32_t* bb = Bt + (n0 + nt * 8 + fr) * RW + kw + fc;
                b[0] = bb[0];
                b[1] = bb[4];
#pragma unroll
                for (int mt = 0; mt < 2; mt++)
                    mma16816(acc[mt][nt], a[mt], b);
            }
        }
    }

    // ---- epilogue: scatter to g_node_p / g_edge_p ----
    // D frag: d0,d1 -> row fr, cols 2*fc, 2*fc+1 ; d2,d3 -> row fr+8.
#pragma unroll
    for (int mt = 0; mt < 2; mt++) {
#pragma unroll
        for (int half = 0; half < 2; half++) {
            int mrow = m0 + mt * 16 + half * 8 + fr;
            int r = rows[mrow];
            if (r < 0) continue;
            float* dst = (j == 4) ? (g_node_p + (size_t)r * FF)
                                  : (g_edge_p + ((size_t)r * TT + j) * FF);
#pragma unroll
            for (int nt = 0; nt < 8; nt++) {
                *(float2*)(dst + n0 + nt * 8 + fc * 2) =
                    make_float2(acc[mt][nt][half * 2], acc[mt][nt][half * 2 + 1]);
            }
        }
    }
}

// ---------------------------------------------------------------------------
// Scores + softmax over HEAD axis. One warp/node, lane = t*8+h.
// ---------------------------------------------------------------------------
__global__ void k_attn(float* __restrict__ out, int n) {
    int warp = (int)((blockIdx.x * blockDim.x + threadIdx.x) >> 5);
    int lane = threadIdx.x & 31;
    if (warp >= n) return;
    int t = lane >> 3;
    int h = lane & 7;

    const float* np = g_node_p + (size_t)warp * FF + h * DD;
    const float* ep = g_edge_p + ((size_t)warp * TT + t) * FF + h * DD;

    float s = 0.f;
#pragma unroll
    for (int q = 0; q < 4; q++) {
        float4 a = *(const float4*)(np + q * 4);
        float4 b = *(const float4*)(ep + q * 4);
        s += a.x * b.x + a.y * b.y + a.z * b.z + a.w * b.w;
    }
    s *= 0.25f;  // 1/sqrt(16)

    float m = s;
#pragma unroll
    for (int o = 4; o >= 1; o >>= 1)
        m = fmaxf(m, __shfl_xor_sync(0xffffffffu, m, o, 8));
    float e = expf(s - m);
    float sum = e;
#pragma unroll
    for (int o = 4; o >= 1; o >>= 1)
        sum += __shfl_xor_sync(0xffffffffu, sum, o, 8);

    out[(size_t)warp * (TT * HH) + lane] = e / sum;
}

// ---------------------------------------------------------------------------
extern "C" void kernel_launch(void* const* d_in, const int* in_sizes, int n_in,
                              void* d_out, int out_size) {
    const float* feature   = (const float*)d_in[0];
    const float* edge_fea  = (const float*)d_in[1];
    const int*   mask      = (const int*)d_in[2];
    const float* node_proj = (const float*)d_in[3];
    const float* edge_proj = (const float*)d_in[4];
    float* out = (float*)d_out;

    const int n = in_sizes[2];

    static int smem_set = 0;
    if (!smem_set) {
        cudaFuncSetAttribute(k_gemm_mma, cudaFuncAttributeMaxDynamicSharedMemorySize, SMEM_BYTES);
        smem_set = 1;
    }

    k_zero<<<1, 32>>>();
    k_scatter<<<(n + 255) / 256, 256>>>(mask, n);

    dim3 grid((n + 127) / 128, TT, 5);
    k_gemm_mma<<<grid, 256, SMEM_BYTES>>>(feature, edge_fea, node_proj, edge_proj);

    k_attn<<<(n + 7) / 8, 256>>>(out, n);
}